// round 8
// baseline (speedup 1.0000x reference)
#include <cuda_runtime.h>
#include <cuda_fp16.h>

#define BOHR        0.52917721067f
#define A_MUTUAL    0.39f
#define MAX_NODES   262144

#define SMEM_Q_NODES 110592                 // fp16 q entries resident in smem
#define SMEM_BYTES   (SMEM_Q_NODES * 2)     // 221184 B dynamic smem
#define EDGE_GRID    148
#define EDGE_BLOCK   1024

// Scratch (no allocations allowed).
__device__ float4 g_pack[MAX_NODES];   // {mu.x, mu.y, mu.z, q=rsqrt(pol_bohr)}
__device__ __half g_q16[MAX_NODES];    // dense fp16 q
__device__ float4 g_acc[MAX_NODES];    // field accumulator (w unused)

__global__ void pack_kernel(const float* __restrict__ pol,
                            const float* __restrict__ mu,
                            int n_nodes)
{
    int t  = blockIdx.x * blockDim.x + threadIdx.x;
    int i0 = 2 * t;
    if (i0 >= n_nodes) return;
    const float inv_bohr3 = 1.0f / (BOHR * BOHR * BOHR);
    const float4 zero4 = make_float4(0.f, 0.f, 0.f, 0.f);

    if (i0 + 1 < n_nodes) {
        float2 pp = *(const float2*)(pol + i0);
        float2 m0 = *(const float2*)(mu + 3 * i0 + 0);
        float2 m1 = *(const float2*)(mu + 3 * i0 + 2);
        float2 m2 = *(const float2*)(mu + 3 * i0 + 4);

        float q0 = rsqrtf(pp.x * inv_bohr3);
        float q1 = rsqrtf(pp.y * inv_bohr3);

        g_pack[i0 + 0] = make_float4(m0.x, m0.y, m1.x, q0);
        g_pack[i0 + 1] = make_float4(m1.y, m2.x, m2.y, q1);
        *(__half2*)(&g_q16[i0]) = __floats2half2_rn(q0, q1);
        g_acc[i0 + 0] = zero4;
        g_acc[i0 + 1] = zero4;
    } else {
        float q = rsqrtf(pol[i0] * inv_bohr3);
        g_pack[i0] = make_float4(mu[3 * i0], mu[3 * i0 + 1], mu[3 * i0 + 2], q);
        g_q16[i0]  = __float2half_rn(q);
        g_acc[i0]  = zero4;
    }
}

// float4 gather that bypasses L1 allocation.
__device__ __forceinline__ float4 ldg_na(const float4* p)
{
    float4 v;
    asm("ld.global.nc.L1::no_allocate.v4.f32 {%0,%1,%2,%3}, [%4];"
        : "=f"(v.x), "=f"(v.y), "=f"(v.z), "=f"(v.w) : "l"(p));
    return v;
}

// Persistent edge kernel: smem-resident q table for src < SMEM_Q_NODES.
__global__ void __launch_bounds__(EDGE_BLOCK, 1)
edge_kernel(const int*   __restrict__ edge_src,
            const int*   __restrict__ edge_dst,
            const float* __restrict__ distances,
            const float* __restrict__ vec,
            int n_edges)
{
    extern __shared__ __half s_q[];

    // Cooperative smem fill: 221184B as int4 chunks (all within g_q16's
    // MAX_NODES extent, so always in-bounds).
    {
        int4* s4 = (int4*)s_q;
        const int4* g4 = (const int4*)g_q16;
        const int n4 = SMEM_BYTES / 16;
        for (int i = threadIdx.x; i < n4; i += EDGE_BLOCK)
            s4[i] = g4[i];
    }
    __syncthreads();

    const float inv_bohr = 1.0f / BOHR;
    const int stride = EDGE_GRID * EDGE_BLOCK;

    for (int e = blockIdx.x * EDGE_BLOCK + threadIdx.x; e < n_edges; e += stride) {
        int   src = __ldcs(edge_src + e);
        int   dst = __ldcs(edge_dst + e);
        float rij = __ldcs(distances + e) * inv_bohr;
        float vx  = __ldcs(vec + 3 * e + 0) * inv_bohr;
        float vy  = __ldcs(vec + 3 * e + 1) * inv_bohr;
        float vz  = __ldcs(vec + 3 * e + 2) * inv_bohr;

        float4 pd = ldg_na(&g_pack[dst]);

        float qs;
        if (src < SMEM_Q_NODES)
            qs = __half2float(s_q[src]);           // LDS: ~4 cyc/warp
        else
            qs = __half2float(g_q16[src]);         // L2 gather fallback

        float inv_sqrt_alpha = qs * pd.w;
        float rij2 = rij * rij;
        float rij3 = rij2 * rij;
        float au3  = A_MUTUAL * rij3 * inv_sqrt_alpha;

        float eexp = __expf(-au3);
        float lam3 = 1.0f - eexp;
        float lam5 = 1.0f - (1.0f + au3) * eexp;

        float inv_r3 = 1.0f / rij3;
        float inv_r5 = inv_r3 / rij2;

        float dot = vx * pd.x + vy * pd.y + vz * pd.z;

        float c3 = lam3 * inv_r3;
        float c5 = 3.0f * lam5 * inv_r5 * dot;

        float cx = c3 * pd.x - c5 * vx;
        float cy = c3 * pd.y - c5 * vy;
        float cz = c3 * pd.z - c5 * vz;

        float4* dstp = &g_acc[src];
        asm volatile("red.global.add.v4.f32 [%0], {%1, %2, %3, %4};"
                     :: "l"(dstp), "f"(cx), "f"(cy), "f"(cz), "f"(0.0f)
                     : "memory");
    }
}

// final: out = mu*q^2 + acc   (1/pol_bohr == q^2). 2 nodes/thread.
__global__ void final_kernel(float* __restrict__ out, int n_nodes)
{
    int t  = blockIdx.x * blockDim.x + threadIdx.x;
    int i0 = 2 * t;
    if (i0 >= n_nodes) return;

    if (i0 + 1 < n_nodes) {
        float4 p0 = g_pack[i0 + 0];
        float4 p1 = g_pack[i0 + 1];
        float4 a0 = g_acc[i0 + 0];
        float4 a1 = g_acc[i0 + 1];
        float ip0 = p0.w * p0.w;
        float ip1 = p1.w * p1.w;
        float2* o = (float2*)(out + 3 * i0);
        o[0] = make_float2(p0.x * ip0 + a0.x, p0.y * ip0 + a0.y);
        o[1] = make_float2(p0.z * ip0 + a0.z, p1.x * ip1 + a1.x);
        o[2] = make_float2(p1.y * ip1 + a1.y, p1.z * ip1 + a1.z);
    } else {
        float4 p = g_pack[i0];
        float4 a = g_acc[i0];
        float ip = p.w * p.w;
        out[3 * i0 + 0] = p.x * ip + a.x;
        out[3 * i0 + 1] = p.y * ip + a.y;
        out[3 * i0 + 2] = p.z * ip + a.z;
    }
}

extern "C" void kernel_launch(void* const* d_in, const int* in_sizes, int n_in,
                              void* d_out, int out_size)
{
    const int*   edge_src = (const int*)  d_in[1];
    const int*   edge_dst = (const int*)  d_in[2];
    const float* dists    = (const float*)d_in[3];
    const float* vec      = (const float*)d_in[4];
    const float* pol      = (const float*)d_in[5];
    const float* mu       = (const float*)d_in[6];
    float*       out      = (float*)d_out;

    int n_edges = in_sizes[3];
    int n_nodes = in_sizes[5];

    static int smem_set = 0;
    if (!smem_set) {
        cudaFuncSetAttribute(edge_kernel,
                             cudaFuncAttributeMaxDynamicSharedMemorySize,
                             SMEM_BYTES);
        smem_set = 1;
    }

    int tb = 256;
    int nodes2 = (n_nodes + 1) / 2;
    pack_kernel<<<(nodes2 + tb - 1) / tb, tb>>>(pol, mu, n_nodes);
    edge_kernel<<<EDGE_GRID, EDGE_BLOCK, SMEM_BYTES>>>(edge_src, edge_dst,
                                                       dists, vec, n_edges);
    final_kernel<<<(nodes2 + tb - 1) / tb, tb>>>(out, n_nodes);
}

// round 9
// speedup vs baseline: 1.6828x; 1.6828x over previous
#include <cuda_runtime.h>
#include <cuda_fp16.h>

#define BOHR        0.52917721067f
#define A_MUTUAL    0.39f
#define MAX_NODES   262144

// Scratch (no allocations allowed).
__device__ float4 g_pack[MAX_NODES];   // {mu.x, mu.y, mu.z, q=rsqrt(pol_bohr)}
__device__ __half g_q16[MAX_NODES];    // dense fp16 q (L1-friendly src gather)
__device__ float4 g_acc[MAX_NODES];    // field accumulator (w unused)

// 1 node/thread (R4 shape — fastest measured pack); acc zeroed via memset.
__global__ void pack_kernel(const float* __restrict__ pol,
                            const float* __restrict__ mu,
                            int n_nodes)
{
    int i = blockIdx.x * blockDim.x + threadIdx.x;
    if (i >= n_nodes) return;
    const float inv_bohr3 = 1.0f / (BOHR * BOHR * BOHR);
    float q = rsqrtf(pol[i] * inv_bohr3);
    float4 p;
    p.x = mu[3 * i + 0];
    p.y = mu[3 * i + 1];
    p.z = mu[3 * i + 2];
    p.w = q;
    g_pack[i] = p;
    g_q16[i]  = __float2half_rn(q);
}

// float4 gather that bypasses L1 allocation (3.2MB ws can never be L1-resident;
// don't let it evict the q lines).
__device__ __forceinline__ float4 ldg_na(const float4* p)
{
    float4 v;
    asm("ld.global.nc.L1::no_allocate.v4.f32 {%0,%1,%2,%3}, [%4];"
        : "=f"(v.x), "=f"(v.y), "=f"(v.z), "=f"(v.w) : "l"(p));
    return v;
}

// R4/R7-exact edge kernel (proven best: 1 edge/thread, L1-policy segregation).
__global__ void edge_kernel(const int*   __restrict__ edge_src,
                            const int*   __restrict__ edge_dst,
                            const float* __restrict__ distances,
                            const float* __restrict__ vec,
                            int n_edges)
{
    const float inv_bohr = 1.0f / BOHR;

    int e = blockIdx.x * blockDim.x + threadIdx.x;
    if (e >= n_edges) return;

    int   src = __ldcs(edge_src + e);
    int   dst = __ldcs(edge_dst + e);
    float rij = __ldcs(distances + e) * inv_bohr;
    float vx  = __ldcs(vec + 3 * e + 0) * inv_bohr;
    float vy  = __ldcs(vec + 3 * e + 1) * inv_bohr;
    float vz  = __ldcs(vec + 3 * e + 2) * inv_bohr;

    float4 pd = ldg_na(&g_pack[dst]);
    float  qs = __half2float(g_q16[src]);

    float inv_sqrt_alpha = qs * pd.w;
    float rij2 = rij * rij;
    float rij3 = rij2 * rij;
    float au3  = A_MUTUAL * rij3 * inv_sqrt_alpha;

    float eexp = __expf(-au3);
    float lam3 = 1.0f - eexp;
    float lam5 = 1.0f - (1.0f + au3) * eexp;

    float inv_r3 = 1.0f / rij3;
    float inv_r5 = inv_r3 / rij2;

    float dot = vx * pd.x + vy * pd.y + vz * pd.z;

    float c3 = lam3 * inv_r3;
    float c5 = 3.0f * lam5 * inv_r5 * dot;

    float cx = c3 * pd.x - c5 * vx;
    float cy = c3 * pd.y - c5 * vy;
    float cz = c3 * pd.z - c5 * vz;

    float4* dstp = &g_acc[src];
    asm volatile("red.global.add.v4.f32 [%0], {%1, %2, %3, %4};"
                 :: "l"(dstp), "f"(cx), "f"(cy), "f"(cz), "f"(0.0f)
                 : "memory");
}

// final: out = mu*q^2 + acc   (1/pol_bohr == q^2). 2 nodes/thread (R7 winner).
__global__ void final_kernel(float* __restrict__ out, int n_nodes)
{
    int t  = blockIdx.x * blockDim.x + threadIdx.x;
    int i0 = 2 * t;
    if (i0 >= n_nodes) return;

    if (i0 + 1 < n_nodes) {
        float4 p0 = g_pack[i0 + 0];
        float4 p1 = g_pack[i0 + 1];
        float4 a0 = g_acc[i0 + 0];
        float4 a1 = g_acc[i0 + 1];
        float ip0 = p0.w * p0.w;
        float ip1 = p1.w * p1.w;
        float2* o = (float2*)(out + 3 * i0);
        o[0] = make_float2(p0.x * ip0 + a0.x, p0.y * ip0 + a0.y);
        o[1] = make_float2(p0.z * ip0 + a0.z, p1.x * ip1 + a1.x);
        o[2] = make_float2(p1.y * ip1 + a1.y, p1.z * ip1 + a1.z);
    } else {
        float4 p = g_pack[i0];
        float4 a = g_acc[i0];
        float ip = p.w * p.w;
        out[3 * i0 + 0] = p.x * ip + a.x;
        out[3 * i0 + 1] = p.y * ip + a.y;
        out[3 * i0 + 2] = p.z * ip + a.z;
    }
}

extern "C" void kernel_launch(void* const* d_in, const int* in_sizes, int n_in,
                              void* d_out, int out_size)
{
    const int*   edge_src = (const int*)  d_in[1];
    const int*   edge_dst = (const int*)  d_in[2];
    const float* dists    = (const float*)d_in[3];
    const float* vec      = (const float*)d_in[4];
    const float* pol      = (const float*)d_in[5];
    const float* mu       = (const float*)d_in[6];
    float*       out      = (float*)d_out;

    int n_edges = in_sizes[3];
    int n_nodes = in_sizes[5];

    static void* acc_ptr = nullptr;
    if (!acc_ptr)
        cudaGetSymbolAddress(&acc_ptr, g_acc);

    int tb = 256;
    // Zero the accumulator with an async memset node (HW rate, graph-capturable).
    cudaMemsetAsync(acc_ptr, 0, (size_t)n_nodes * sizeof(float4));
    pack_kernel<<<(n_nodes + tb - 1) / tb, tb>>>(pol, mu, n_nodes);
    edge_kernel<<<(n_edges + tb - 1) / tb, tb>>>(edge_src, edge_dst, dists, vec, n_edges);
    final_kernel<<<((n_nodes + 1) / 2 + tb - 1) / tb, tb>>>(out, n_nodes);
}